// round 14
// baseline (speedup 1.0000x reference)
#include <cuda_runtime.h>
#include <cstdint>

#define B_    16
#define FIN_  16
#define FOUT_ 16
#define H_    384
#define W_    384
#define LAT_  512
#define NMIX_ 8
#define HW_   (H_ * W_)        // 147456
#define PLANE4_ (HW_ / 4)      // 36864 float4 groups per channel plane

__device__ __forceinline__ unsigned long long pack2(float v) {
    unsigned int u = __float_as_uint(v);
    return ((unsigned long long)u << 32) | (unsigned long long)u;
}

__device__ __forceinline__ unsigned long long ffma2(unsigned long long a,
                                                    unsigned long long b,
                                                    unsigned long long c) {
    unsigned long long d;
    asm("fma.rn.f32x2 %0, %1, %2, %3;" : "=l"(d) : "l"(a), "l"(b), "l"(c));
    return d;
}

__device__ __forceinline__ void prefetch_l2(const void* p) {
    asm volatile("prefetch.global.L2 [%0];" :: "l"(p));
}

// ---------------------------------------------------------------------------
// Fused kernel, i-outer accumulation:
//   (0) 16 prefetch.global.L2 for this tile (no reg/scoreboard cost) so the
//       DRAM fetch overlaps phase-1 and the loop's LDGs hit L2;
//   (1) phase-1: warp-parallel mix dots -> K (TRANSPOSED skt[i][o]) + bias;
//   (2) i-outer loop: per channel 1 LDG.128 + 8 LDS.128 (contiguous k col)
//       + 32 ffma2 into 32 packed accumulators -> load issue is spread
//       through the whole warp lifetime instead of one front burst;
//   (3) 16 STG.128.
//   ~95-110 regs -> occ 2, no spill.
// ---------------------------------------------------------------------------
__global__ void __launch_bounds__(256, 2)
mixconv_fused(const float* __restrict__ x,
              const float* __restrict__ lat,
              const float* __restrict__ kernel_mix,
              const float* __restrict__ bias_mix,
              const float* __restrict__ w_dyn,
              const float* __restrict__ b_dyn,
              float* __restrict__ out) {
    __shared__ float s_mix[NMIX_];
    __shared__ __align__(16) unsigned long long skt[FIN_ * FOUT_]; // [i][o] {k,k}
    __shared__ unsigned long long sb[FOUT_];

    const int b    = blockIdx.y;
    const int t    = threadIdx.x;
    const int w    = t >> 5;      // warp id 0..7 == mixture index
    const int lane = t & 31;

    const int p = blockIdx.x * 256 + t;             // float4 group in plane

    const ulonglong2* __restrict__ xp =
        (const ulonglong2*)(x + (size_t)b * FIN_ * HW_);
    ulonglong2* __restrict__ op =
        (ulonglong2*)(out + (size_t)b * FOUT_ * HW_);
    const ulonglong2* __restrict__ skt2 = (const ulonglong2*)skt;

    // ---- (0) prefetch this tile's 16 channel lines into L2 -------------
    #pragma unroll
    for (int i = 0; i < FIN_; ++i)
        prefetch_l2(xp + (size_t)i * PLANE4_ + p);

    // ---- (1a) mix[b][w] via warp-parallel dot product (overlaps fetch) --
    {
        const float* __restrict__ lp = lat + b * LAT_;
        const float* __restrict__ wp = w_dyn + w * LAT_;
        float s = 0.f;
        #pragma unroll
        for (int j = 0; j < LAT_ / 32; ++j)
            s = fmaf(__ldg(lp + lane + 32 * j), __ldg(wp + lane + 32 * j), s);
        #pragma unroll
        for (int off = 16; off > 0; off >>= 1)
            s += __shfl_xor_sync(0xffffffffu, s, off);
        if (lane == 0) s_mix[w] = s + __ldg(b_dyn + w);
    }
    __syncthreads();

    // ---- (1b) transposed per-sample kernel + bias into smem -------------
    {
        // thread t -> skt[i][o] with i = t>>4, o = t&15
        const int i = t >> 4;
        const int o = t & 15;
        float s = 0.f;
        #pragma unroll
        for (int m = 0; m < NMIX_; ++m)
            s = fmaf(s_mix[m], __ldg(kernel_mix + m * (FOUT_ * FIN_) + o * FIN_ + i), s);
        skt[t] = pack2(s);
        if (t < FOUT_) {
            float sv = 0.f;
            #pragma unroll
            for (int m = 0; m < NMIX_; ++m)
                sv = fmaf(s_mix[m], __ldg(bias_mix + m * FOUT_ + t), sv);
            sb[t] = pack2(sv);
        }
    }
    __syncthreads();

    // ---- (2) i-outer accumulation: loads spread through lifetime --------
    unsigned long long acc_lo[FOUT_], acc_hi[FOUT_];
    #pragma unroll
    for (int o = 0; o < FOUT_; ++o) {
        acc_lo[o] = sb[o];
        acc_hi[o] = acc_lo[o];
    }

    #pragma unroll
    for (int i = 0; i < FIN_; ++i) {
        ulonglong2 v = xp[(size_t)i * PLANE4_ + p];   // L2 hit (prefetched)
        #pragma unroll
        for (int j = 0; j < FOUT_ / 2; ++j) {
            ulonglong2 kk = skt2[i * (FOUT_ / 2) + j]; // LDS.128: k[i][2j],k[i][2j+1]
            acc_lo[2 * j]     = ffma2(kk.x, v.x, acc_lo[2 * j]);
            acc_hi[2 * j]     = ffma2(kk.x, v.y, acc_hi[2 * j]);
            acc_lo[2 * j + 1] = ffma2(kk.y, v.x, acc_lo[2 * j + 1]);
            acc_hi[2 * j + 1] = ffma2(kk.y, v.y, acc_hi[2 * j + 1]);
        }
    }

    // ---- (3) stores ------------------------------------------------------
    #pragma unroll
    for (int o = 0; o < FOUT_; ++o) {
        ulonglong2 r;
        r.x = acc_lo[o];
        r.y = acc_hi[o];
        op[(size_t)o * PLANE4_ + p] = r;
    }
}

// ---------------------------------------------------------------------------
extern "C" void kernel_launch(void* const* d_in, const int* in_sizes, int n_in,
                              void* d_out, int out_size) {
    const float* x          = (const float*)d_in[0];  // [16,16,384,384]
    const float* lat        = (const float*)d_in[1];  // [16,512]
    const float* kernel_mix = (const float*)d_in[2];  // [8,16,16]
    const float* bias_mix   = (const float*)d_in[3];  // [8,16]
    const float* w_dyn      = (const float*)d_in[4];  // [8,512]
    const float* b_dyn      = (const float*)d_in[5];  // [8]
    float* out = (float*)d_out;

    dim3 grid(PLANE4_ / 256, B_);   // (144, 16) = 2304 blocks, one tile each
    mixconv_fused<<<grid, 256>>>(x, lat, kernel_mix, bias_mix, w_dyn, b_dyn, out);
}

// round 17
// speedup vs baseline: 1.0588x; 1.0588x over previous
#include <cuda_runtime.h>
#include <cstdint>

#define B_    16
#define FIN_  16
#define FOUT_ 16
#define H_    384
#define W_    384
#define LAT_  512
#define NMIX_ 8
#define HW_   (H_ * W_)        // 147456
#define PLANE4_ (HW_ / 4)      // 36864 float4 groups per channel plane

__device__ __forceinline__ unsigned long long pack2(float v) {
    unsigned int u = __float_as_uint(v);
    return ((unsigned long long)u << 32) | (unsigned long long)u;
}

__device__ __forceinline__ unsigned long long ffma2(unsigned long long a,
                                                    unsigned long long b,
                                                    unsigned long long c) {
    unsigned long long d;
    asm("fma.rn.f32x2 %0, %1, %2, %3;" : "=l"(d) : "l"(a), "l"(b), "l"(c));
    return d;
}

// Streaming (evict-first) 16B load/store for zero-reuse data.
__device__ __forceinline__ ulonglong2 ldcs128(const ulonglong2* p) {
    ulonglong2 v;
    asm volatile("ld.global.cs.v2.u64 {%0, %1}, [%2];"
                 : "=l"(v.x), "=l"(v.y) : "l"(p));
    return v;
}
__device__ __forceinline__ void stcs128(ulonglong2* p, ulonglong2 v) {
    asm volatile("st.global.cs.v2.u64 [%0], {%1, %2};"
                 :: "l"(p), "l"(v.x), "l"(v.y) : "memory");
}

// ---------------------------------------------------------------------------
// R13 structure (proven 45.15us kernel) + streaming cache hints:
//   (0) issue the 16 x-tile LDG.128 FIRST with .cs (evict-first; x is
//       read-once so don't let the stream thrash L2);
//   (1) phase-1 runs while those DRAM loads are in flight (barriers drain
//       STS, not LDG; scoreboard wait lands at first ffma2 consumption);
//   (2) ffma2 streaming body; stores use .cs (write-once, never re-read).
//   L2 capacity is preserved for the phase-1 broadcast set that all 2304
//   blocks re-read (lat/w_dyn/kernel_mix).
// ---------------------------------------------------------------------------
__global__ void __launch_bounds__(256, 2)
mixconv_fused(const float* __restrict__ x,
              const float* __restrict__ lat,
              const float* __restrict__ kernel_mix,
              const float* __restrict__ bias_mix,
              const float* __restrict__ w_dyn,
              const float* __restrict__ b_dyn,
              float* __restrict__ out) {
    __shared__ float s_mix[NMIX_];
    __shared__ __align__(16) unsigned long long sk[FOUT_ * FIN_]; // packed {k,k}
    __shared__ unsigned long long sb[FOUT_];

    const int b    = blockIdx.y;
    const int t    = threadIdx.x;
    const int w    = t >> 5;      // warp id 0..7 == mixture index
    const int lane = t & 31;

    // ---- (0) Issue x-tile loads first: independent of phase-1 ----------
    const int p = blockIdx.x * 256 + t;             // float4 group in plane

    const ulonglong2* __restrict__ xp =
        (const ulonglong2*)(x + (size_t)b * FIN_ * HW_);
    ulonglong2* __restrict__ op =
        (ulonglong2*)(out + (size_t)b * FOUT_ * HW_);
    const ulonglong2* __restrict__ sk2 = (const ulonglong2*)sk;

    unsigned long long in_lo[FIN_], in_hi[FIN_];
    #pragma unroll
    for (int i = 0; i < FIN_; ++i) {
        ulonglong2 v = ldcs128(xp + (size_t)i * PLANE4_ + p);
        in_lo[i] = v.x;
        in_hi[i] = v.y;
    }

    // ---- (1a) mix[b][w] via warp-parallel dot product (overlaps loads) --
    {
        const float* __restrict__ lp = lat + b * LAT_;
        const float* __restrict__ wp = w_dyn + w * LAT_;
        float s = 0.f;
        #pragma unroll
        for (int j = 0; j < LAT_ / 32; ++j)
            s = fmaf(__ldg(lp + lane + 32 * j), __ldg(wp + lane + 32 * j), s);
        #pragma unroll
        for (int off = 16; off > 0; off >>= 1)
            s += __shfl_xor_sync(0xffffffffu, s, off);
        if (lane == 0) s_mix[w] = s + __ldg(b_dyn + w);
    }
    __syncthreads();

    // ---- (1b) per-sample kernel + bias into smem ------------------------
    {
        float s = 0.f;
        #pragma unroll
        for (int m = 0; m < NMIX_; ++m)
            s = fmaf(s_mix[m], __ldg(kernel_mix + m * (FOUT_ * FIN_) + t), s);
        sk[t] = pack2(s);
        if (t < FOUT_) {
            float sv = 0.f;
            #pragma unroll
            for (int m = 0; m < NMIX_; ++m)
                sv = fmaf(s_mix[m], __ldg(bias_mix + m * FOUT_ + t), sv);
            sb[t] = pack2(sv);
        }
    }
    __syncthreads();

    // ---- (2) streaming body: consume loads (arrived during phase-1) -----
    #pragma unroll
    for (int o = 0; o < FOUT_; ++o) {
        unsigned long long alo = sb[o];
        unsigned long long ahi = alo;
        #pragma unroll
        for (int j = 0; j < FIN_ / 2; ++j) {
            ulonglong2 kk = sk2[o * (FIN_ / 2) + j];   // LDS.128: two {k,k}
            alo = ffma2(kk.x, in_lo[2 * j],     alo);
            ahi = ffma2(kk.x, in_hi[2 * j],     ahi);
            alo = ffma2(kk.y, in_lo[2 * j + 1], alo);
            ahi = ffma2(kk.y, in_hi[2 * j + 1], ahi);
        }
        ulonglong2 r;
        r.x = alo;
        r.y = ahi;
        stcs128(op + (size_t)o * PLANE4_ + p, r);
    }
}

// ---------------------------------------------------------------------------
extern "C" void kernel_launch(void* const* d_in, const int* in_sizes, int n_in,
                              void* d_out, int out_size) {
    const float* x          = (const float*)d_in[0];  // [16,16,384,384]
    const float* lat        = (const float*)d_in[1];  // [16,512]
    const float* kernel_mix = (const float*)d_in[2];  // [8,16,16]
    const float* bias_mix   = (const float*)d_in[3];  // [8,16]
    const float* w_dyn      = (const float*)d_in[4];  // [8,512]
    const float* b_dyn      = (const float*)d_in[5];  // [8]
    float* out = (float*)d_out;

    dim3 grid(PLANE4_ / 256, B_);   // (144, 16) = 2304 blocks, one tile each
    mixconv_fused<<<grid, 256>>>(x, lat, kernel_mix, bias_mix, w_dyn, b_dyn, out);
}